// round 1
// baseline (speedup 1.0000x reference)
#include <cuda_runtime.h>
#include <math.h>

// Problem constants
#define B_   4
#define L_   2048
#define D_   1024
#define H_   16
#define DFF_ 4096
#define HD_  64
#define M_   (B_*L_)        // 8192 rows

// ---------------- scratch (static device allocations; no cudaMalloc) ----------------
__device__ float g_qkv[(size_t)M_ * 3 * D_];            // [B,L,3D]   100.7 MB
__device__ float g_scores[(size_t)B_ * H_ * L_ * L_];   // [B,H,L,L]  1073 MB
__device__ float g_ctx[(size_t)M_ * D_];                // [B,L,D]
__device__ float g_x1[(size_t)M_ * D_];                 // LN1 output
__device__ float g_h[(size_t)M_ * DFF_];                // FFN hidden
__device__ float g_t[(size_t)M_ * D_];                  // attn_out / ffn_out tmp

// ---------------- helpers ----------------
__device__ __forceinline__ unsigned f2tf(float x) {
    unsigned r;
    asm("cvt.rna.tf32.f32 %0, %1;" : "=r"(r) : "f"(x));
    return r;
}

__device__ __forceinline__ void mma_tf32(float* d, const unsigned* a, const unsigned* b) {
    asm volatile(
        "mma.sync.aligned.m16n8k8.row.col.f32.tf32.tf32.f32 "
        "{%0,%1,%2,%3}, {%4,%5,%6,%7}, {%8,%9}, {%0,%1,%2,%3};\n"
        : "+f"(d[0]), "+f"(d[1]), "+f"(d[2]), "+f"(d[3])
        : "r"(a[0]), "r"(a[1]), "r"(a[2]), "r"(a[3]), "r"(b[0]), "r"(b[1]));
}

template<int OP>
__device__ __forceinline__ float epi(float v, float b) {
    if (OP >= 1) v += b;
    if (OP == 2) v = 0.5f * v * (1.0f + erff(v * 0.7071067811865475f));
    return v;
}

// ---------------- TF32 GEMM ----------------
// C = A(MxK, row-major, lda) * B  with B row-major KxN (NN) or row-major NxK (NT: C=A*B^T)
// Block tile 128 x BN, BK=32, 8 warps (4x2), warp tile 32 x (BN/2).
// All problem dims are exact multiples of tiles -> no bounds checks.
// Batched via blockIdx.z: offset = (z>>4)*s?b + (z&15)*s?h  (b = z/H, h = z%H).
template<int BN, bool TRANSB, int OP>
__global__ void __launch_bounds__(256)
gemm_tf32(const float* __restrict__ A, const float* __restrict__ Bm,
          const float* __restrict__ bias, float* __restrict__ C,
          int K, int lda, int ldb, int ldc,
          long sAb, long sAh, long sBb, long sBh, long sCb, long sCh)
{
    constexpr int BM  = 128, BK = 32;
    constexpr int ASR = BK + 4;   // 36: (4*gid+tig) covers all 32 banks -> conflict-free a-frag loads
    constexpr int BSR = BN + 8;   // 136/72: (8*tig+gid) covers all 32 banks -> conflict-free b-frag loads
    constexpr int WN  = BN / 2;
    constexpr int NT  = WN / 8;
    constexpr int NBL = BN / 32;

    __shared__ unsigned As[BM * ASR];
    __shared__ unsigned Bs[BK * BSR];

    const int z = blockIdx.z;
    A  += (long)(z >> 4) * sAb + (long)(z & 15) * sAh;
    Bm += (long)(z >> 4) * sBb + (long)(z & 15) * sBh;
    C  += (long)(z >> 4) * sCb + (long)(z & 15) * sCh;

    const int t    = threadIdx.x;
    const int lane = t & 31;
    const int wid  = t >> 5;
    const int gid  = lane >> 2, tig = lane & 3;
    const int wm   = (wid & 3) * 32;
    const int wn   = (wid >> 2) * WN;
    const long bm0 = (long)blockIdx.y * BM;
    const long bn0 = (long)blockIdx.x * BN;

    float acc[2][NT][4];
#pragma unroll
    for (int i = 0; i < 2; i++)
#pragma unroll
        for (int j = 0; j < NT; j++)
#pragma unroll
            for (int k = 0; k < 4; k++) acc[i][j][k] = 0.f;

    for (int k0 = 0; k0 < K; k0 += BK) {
        // prefetch into registers
        float4 av[4];
#pragma unroll
        for (int i = 0; i < 4; i++) {
            int idx = t + i * 256;
            int r = idx >> 3, c = (idx & 7) << 2;
            av[i] = *(const float4*)(A + (bm0 + r) * lda + k0 + c);
        }
        float4 bv[NBL];
#pragma unroll
        for (int i = 0; i < NBL; i++) {
            int idx = t + i * 256;
            if (!TRANSB) {
                int r = idx / (BN / 4), c = (idx % (BN / 4)) << 2;
                bv[i] = *(const float4*)(Bm + (long)(k0 + r) * ldb + bn0 + c);
            } else {
                int n = idx >> 3, c = (idx & 7) << 2;
                bv[i] = *(const float4*)(Bm + (bn0 + n) * ldb + k0 + c);
            }
        }
        __syncthreads();
#pragma unroll
        for (int i = 0; i < 4; i++) {
            int idx = t + i * 256;
            int r = idx >> 3, c = (idx & 7) << 2;
            uint4 u = make_uint4(f2tf(av[i].x), f2tf(av[i].y), f2tf(av[i].z), f2tf(av[i].w));
            *(uint4*)&As[r * ASR + c] = u;
        }
#pragma unroll
        for (int i = 0; i < NBL; i++) {
            int idx = t + i * 256;
            if (!TRANSB) {
                int r = idx / (BN / 4), c = (idx % (BN / 4)) << 2;
                uint4 u = make_uint4(f2tf(bv[i].x), f2tf(bv[i].y), f2tf(bv[i].z), f2tf(bv[i].w));
                *(uint4*)&Bs[r * BSR + c] = u;
            } else {
                int n = idx >> 3, c = (idx & 7) << 2;
                Bs[(c + 0) * BSR + n] = f2tf(bv[i].x);
                Bs[(c + 1) * BSR + n] = f2tf(bv[i].y);
                Bs[(c + 2) * BSR + n] = f2tf(bv[i].z);
                Bs[(c + 3) * BSR + n] = f2tf(bv[i].w);
            }
        }
        __syncthreads();
#pragma unroll
        for (int kk = 0; kk < 4; kk++) {
            const int k = kk * 8;
            unsigned af[2][4];
#pragma unroll
            for (int mt = 0; mt < 2; mt++) {
                int r = wm + mt * 16 + gid;
                af[mt][0] = As[r * ASR + k + tig];
                af[mt][1] = As[(r + 8) * ASR + k + tig];
                af[mt][2] = As[r * ASR + k + tig + 4];
                af[mt][3] = As[(r + 8) * ASR + k + tig + 4];
            }
#pragma unroll
            for (int nt = 0; nt < NT; nt++) {
                unsigned bf[2];
                int cb = wn + nt * 8 + gid;
                bf[0] = Bs[(k + tig) * BSR + cb];
                bf[1] = Bs[(k + tig + 4) * BSR + cb];
                mma_tf32(acc[0][nt], af[0], bf);
                mma_tf32(acc[1][nt], af[1], bf);
            }
        }
    }

    // epilogue: c0,c1 at (row g, cols 2t,2t+1); c2,c3 at row g+8
#pragma unroll
    for (int mt = 0; mt < 2; mt++) {
#pragma unroll
        for (int nt = 0; nt < NT; nt++) {
            long r0 = bm0 + wm + mt * 16 + gid;
            long c0 = bn0 + wn + nt * 8 + tig * 2;
            float b0v = 0.f, b1v = 0.f;
            if (OP >= 1) { b0v = bias[c0]; b1v = bias[c0 + 1]; }
            float2 p0, p1;
            p0.x = epi<OP>(acc[mt][nt][0], b0v);
            p0.y = epi<OP>(acc[mt][nt][1], b1v);
            p1.x = epi<OP>(acc[mt][nt][2], b0v);
            p1.y = epi<OP>(acc[mt][nt][3], b1v);
            *(float2*)&C[r0 * ldc + c0]       = p0;
            *(float2*)&C[(r0 + 8) * ldc + c0] = p1;
        }
    }
}

// ---------------- bias + softmax over scores rows (in-place) ----------------
// blockIdx.x = bh*L + q ; row length L_=2048 ; 256 threads x 8 elems
__global__ void __launch_bounds__(256)
softmax_bias(float* __restrict__ S, const float* __restrict__ bt)
{
    const long row = blockIdx.x;
    const int q = (int)(row & (L_ - 1));
    const int h = (int)((row >> 11) & (H_ - 1));
    float* p = S + row * L_;
    const int t = threadIdx.x;
    __shared__ float red[8];

    float v[8];
#pragma unroll
    for (int i = 0; i < 2; i++) {
        int c = (t + i * 256) * 4;
        float4 x = *(const float4*)(p + c);
        float xs[4] = {x.x, x.y, x.z, x.w};
#pragma unroll
        for (int j = 0; j < 4; j++) {
            int rel = c + j - q + 511;
            rel = min(max(rel, 0), 1022);
            v[i * 4 + j] = xs[j] * 0.125f + bt[rel * 16 + h];
        }
    }
    float mx = v[0];
#pragma unroll
    for (int k = 1; k < 8; k++) mx = fmaxf(mx, v[k]);
#pragma unroll
    for (int off = 16; off > 0; off >>= 1)
        mx = fmaxf(mx, __shfl_xor_sync(0xffffffffu, mx, off));
    if ((t & 31) == 0) red[t >> 5] = mx;
    __syncthreads();
    float gmx = red[0];
#pragma unroll
    for (int i = 1; i < 8; i++) gmx = fmaxf(gmx, red[i]);
    __syncthreads();

    float s = 0.f;
#pragma unroll
    for (int k = 0; k < 8; k++) { v[k] = expf(v[k] - gmx); s += v[k]; }
#pragma unroll
    for (int off = 16; off > 0; off >>= 1)
        s += __shfl_xor_sync(0xffffffffu, s, off);
    if ((t & 31) == 0) red[t >> 5] = s;
    __syncthreads();
    float gs = red[0];
#pragma unroll
    for (int i = 1; i < 8; i++) gs += red[i];
    float inv = 1.0f / gs;

#pragma unroll
    for (int i = 0; i < 2; i++) {
        int c = (t + i * 256) * 4;
        float4 o;
        o.x = v[i * 4 + 0] * inv;
        o.y = v[i * 4 + 1] * inv;
        o.z = v[i * 4 + 2] * inv;
        o.w = v[i * 4 + 3] * inv;
        *(float4*)(p + c) = o;
    }
}

// ---------------- residual add + LayerNorm ----------------
// O[r] = LN(X[r] + Y[r]) * gamma + beta ; one block (256 thr) per row of D_=1024
__global__ void __launch_bounds__(256)
add_ln(const float* __restrict__ X, const float* __restrict__ Y,
       const float* __restrict__ gamma, const float* __restrict__ beta,
       float* __restrict__ O)
{
    const long r = blockIdx.x;
    const int t = threadIdx.x;
    __shared__ float red[16];

    float4 a = *(const float4*)(X + r * D_ + t * 4);
    float4 b = *(const float4*)(Y + r * D_ + t * 4);
    float v[4] = {a.x + b.x, a.y + b.y, a.z + b.z, a.w + b.w};

    float s = v[0] + v[1] + v[2] + v[3];
    float s2 = v[0]*v[0] + v[1]*v[1] + v[2]*v[2] + v[3]*v[3];
#pragma unroll
    for (int off = 16; off > 0; off >>= 1) {
        s  += __shfl_xor_sync(0xffffffffu, s, off);
        s2 += __shfl_xor_sync(0xffffffffu, s2, off);
    }
    if ((t & 31) == 0) { red[t >> 5] = s; red[8 + (t >> 5)] = s2; }
    __syncthreads();
    float S = 0.f, S2 = 0.f;
#pragma unroll
    for (int i = 0; i < 8; i++) { S += red[i]; S2 += red[8 + i]; }
    const float mean = S * (1.0f / D_);
    const float var  = S2 * (1.0f / D_) - mean * mean;
    const float rinv = rsqrtf(var + 1e-5f);

    float4 g  = *(const float4*)(gamma + t * 4);
    float4 be = *(const float4*)(beta + t * 4);
    float4 o;
    o.x = (v[0] - mean) * rinv * g.x + be.x;
    o.y = (v[1] - mean) * rinv * g.y + be.y;
    o.z = (v[2] - mean) * rinv * g.z + be.z;
    o.w = (v[3] - mean) * rinv * g.w + be.w;
    *(float4*)(O + r * D_ + t * 4) = o;
}

// ---------------- launcher ----------------
extern "C" void kernel_launch(void* const* d_in, const int* in_sizes, int n_in,
                              void* d_out, int out_size)
{
    const float* x     = (const float*)d_in[0];
    const float* w_qkv = (const float*)d_in[1];
    const float* w_out = (const float*)d_in[2];
    const float* b_out = (const float*)d_in[3];
    const float* bt    = (const float*)d_in[4];
    const float* g1    = (const float*)d_in[5];
    const float* be1   = (const float*)d_in[6];
    const float* w1    = (const float*)d_in[7];
    const float* bf1   = (const float*)d_in[8];
    const float* w2    = (const float*)d_in[9];
    const float* bf2   = (const float*)d_in[10];
    const float* g2    = (const float*)d_in[11];
    const float* be2   = (const float*)d_in[12];
    float* out = (float*)d_out;

    float *qkv, *sc, *ctx, *x1, *hh, *tt;
    cudaGetSymbolAddress((void**)&qkv, g_qkv);
    cudaGetSymbolAddress((void**)&sc,  g_scores);
    cudaGetSymbolAddress((void**)&ctx, g_ctx);
    cudaGetSymbolAddress((void**)&x1,  g_x1);
    cudaGetSymbolAddress((void**)&hh,  g_h);
    cudaGetSymbolAddress((void**)&tt,  g_t);

    const long LL  = (long)L_ * L_;
    const long L3D = (long)L_ * 3 * D_;

    // 1) qkv = x @ w_qkv                          [8192,1024] x [1024,3072]
    gemm_tf32<128, false, 0><<<dim3(3 * D_ / 128, M_ / 128, 1), 256>>>(
        x, w_qkv, nullptr, qkv, D_, D_, 3 * D_, 3 * D_, 0, 0, 0, 0, 0, 0);

    // 2) S[b,h] = Q @ K^T   (batched NT, K=64)    per bh: [2048,64] x [2048,64]^T
    gemm_tf32<128, true, 0><<<dim3(L_ / 128, L_ / 128, B_ * H_), 256>>>(
        qkv, qkv + D_, nullptr, sc, HD_, 3 * D_, 3 * D_, L_,
        L3D, 64, L3D, 64, (long)H_ * LL, LL);

    // 3) softmax(S*scale + bias) in place
    softmax_bias<<<B_ * H_ * L_, 256>>>(sc, bt);

    // 4) ctx[b,:,h*64..] = attn @ V  (batched NN, N=64, K=2048)
    gemm_tf32<64, false, 0><<<dim3(1, L_ / 128, B_ * H_), 256>>>(
        sc, qkv + 2 * D_, nullptr, ctx, L_, L_, 3 * D_, D_,
        (long)H_ * LL, LL, L3D, 64, (long)L_ * D_, 64);

    // 5) attn_out = ctx @ w_out + b_out
    gemm_tf32<128, false, 1><<<dim3(D_ / 128, M_ / 128, 1), 256>>>(
        ctx, w_out, b_out, tt, D_, D_, D_, D_, 0, 0, 0, 0, 0, 0);

    // 6) x1 = LN(x + attn_out)
    add_ln<<<M_, 256>>>(x, tt, g1, be1, x1);

    // 7) h = gelu(x1 @ w_ff1 + b_ff1)
    gemm_tf32<128, false, 2><<<dim3(DFF_ / 128, M_ / 128, 1), 256>>>(
        x1, w1, bf1, hh, D_, D_, DFF_, DFF_, 0, 0, 0, 0, 0, 0);

    // 8) ffn_out = h @ w_ff2 + b_ff2
    gemm_tf32<128, false, 1><<<dim3(D_ / 128, M_ / 128, 1), 256>>>(
        hh, w2, bf2, tt, DFF_, DFF_, D_, D_, 0, 0, 0, 0, 0, 0);

    // 9) out = LN(x1 + ffn_out)
    add_ln<<<M_, 256>>>(x1, tt, g2, be2, out);
}

// round 2
// speedup vs baseline: 1.2776x; 1.2776x over previous
#include <cuda_runtime.h>
#include <math.h>

// Problem constants
#define B_   4
#define L_   2048
#define D_   1024
#define H_   16
#define DFF_ 4096
#define HD_  64
#define M_   (B_*L_)        // 8192 rows

// ---------------- scratch (static device arrays; no cudaMalloc) ----------------
__device__ float g_qkv[(size_t)M_ * 3 * D_];            // [B,L,3D]
__device__ float g_ctx[(size_t)M_ * D_];                // attention context [B,L,D]
__device__ float g_x1[(size_t)M_ * D_];                 // LN1 output
__device__ float g_h[(size_t)M_ * DFF_];                // FFN hidden
__device__ float g_t[(size_t)M_ * D_];                  // attn_out / ffn_out tmp

// ---------------- helpers ----------------
__device__ __forceinline__ unsigned f2tf(float x) {
    unsigned r;
    asm("cvt.rna.tf32.f32 %0, %1;" : "=r"(r) : "f"(x));
    return r;
}

__device__ __forceinline__ void mma_tf32(float* d, const unsigned* a, const unsigned* b) {
    asm volatile(
        "mma.sync.aligned.m16n8k8.row.col.f32.tf32.tf32.f32 "
        "{%0,%1,%2,%3}, {%4,%5,%6,%7}, {%8,%9}, {%0,%1,%2,%3};\n"
        : "+f"(d[0]), "+f"(d[1]), "+f"(d[2]), "+f"(d[3])
        : "r"(a[0]), "r"(a[1]), "r"(a[2]), "r"(a[3]), "r"(b[0]), "r"(b[1]));
}

template<int OP>
__device__ __forceinline__ float epi(float v, float b) {
    if (OP >= 1) v += b;
    if (OP == 2) v = 0.5f * v * (1.0f + erff(v * 0.7071067811865475f));
    return v;
}

// ---------------- TF32 GEMM (NN only), software-pipelined ----------------
// C = A(MxK) * B(KxN) row-major. Block 128x128, BK=32, 8 warps (4x2), warp 32x64.
// Pipeline: regs hold tile i while smem holds tile i-1's data; global loads of
// tile i+1 issue before the compute phase of tile i -> LDG latency overlaps MMA.
template<int OP>
__global__ void __launch_bounds__(256)
gemm_tf32(const float* __restrict__ A, const float* __restrict__ Bm,
          const float* __restrict__ bias, float* __restrict__ C,
          int K, int lda, int ldb, int ldc)
{
    constexpr int BM  = 128, BN = 128, BK = 32;
    constexpr int ASR = BK + 4;   // 36
    constexpr int BSR = BN + 8;   // 136
    constexpr int NT  = 8;

    __shared__ unsigned As[BM * ASR];
    __shared__ unsigned Bs[BK * BSR];

    const int t    = threadIdx.x;
    const int lane = t & 31;
    const int wid  = t >> 5;
    const int gid  = lane >> 2, tig = lane & 3;
    const int wm   = (wid & 3) * 32;
    const int wn   = (wid >> 2) * 64;
    const long bm0 = (long)blockIdx.y * BM;
    const long bn0 = (long)blockIdx.x * BN;

    float acc[2][NT][4];
#pragma unroll
    for (int i = 0; i < 2; i++)
#pragma unroll
        for (int j = 0; j < NT; j++)
#pragma unroll
            for (int k = 0; k < 4; k++) acc[i][j][k] = 0.f;

    float4 av[4], bv[4];
    // prefetch tile 0
#pragma unroll
    for (int i = 0; i < 4; i++) {
        int idx = t + i * 256;
        av[i] = *(const float4*)(A + (bm0 + (idx >> 3)) * lda + ((idx & 7) << 2));
        bv[i] = *(const float4*)(Bm + (long)(idx >> 5) * ldb + bn0 + ((idx & 31) << 2));
    }

    for (int k0 = 0; k0 < K; k0 += BK) {
        __syncthreads();
#pragma unroll
        for (int i = 0; i < 4; i++) {
            int idx = t + i * 256;
            *(uint4*)&As[(idx >> 3) * ASR + ((idx & 7) << 2)] =
                make_uint4(f2tf(av[i].x), f2tf(av[i].y), f2tf(av[i].z), f2tf(av[i].w));
            *(uint4*)&Bs[(idx >> 5) * BSR + ((idx & 31) << 2)] =
                make_uint4(f2tf(bv[i].x), f2tf(bv[i].y), f2tf(bv[i].z), f2tf(bv[i].w));
        }
        __syncthreads();
        if (k0 + BK < K) {
            const int kn = k0 + BK;
#pragma unroll
            for (int i = 0; i < 4; i++) {
                int idx = t + i * 256;
                av[i] = *(const float4*)(A + (bm0 + (idx >> 3)) * lda + kn + ((idx & 7) << 2));
                bv[i] = *(const float4*)(Bm + (long)(kn + (idx >> 5)) * ldb + bn0 + ((idx & 31) << 2));
            }
        }
#pragma unroll
        for (int kk = 0; kk < 4; kk++) {
            const int k = kk * 8;
            unsigned af[2][4];
#pragma unroll
            for (int mt = 0; mt < 2; mt++) {
                int r = wm + mt * 16 + gid;
                af[mt][0] = As[r * ASR + k + tig];
                af[mt][1] = As[(r + 8) * ASR + k + tig];
                af[mt][2] = As[r * ASR + k + tig + 4];
                af[mt][3] = As[(r + 8) * ASR + k + tig + 4];
            }
#pragma unroll
            for (int nt = 0; nt < NT; nt++) {
                unsigned bf[2];
                int cb = wn + nt * 8 + gid;
                bf[0] = Bs[(k + tig) * BSR + cb];
                bf[1] = Bs[(k + tig + 4) * BSR + cb];
                mma_tf32(acc[0][nt], af[0], bf);
                mma_tf32(acc[1][nt], af[1], bf);
            }
        }
    }

#pragma unroll
    for (int mt = 0; mt < 2; mt++) {
#pragma unroll
        for (int nt = 0; nt < NT; nt++) {
            long r0 = bm0 + wm + mt * 16 + gid;
            long c0 = bn0 + wn + nt * 8 + tig * 2;
            float b0v = 0.f, b1v = 0.f;
            if (OP >= 1) { b0v = bias[c0]; b1v = bias[c0 + 1]; }
            float2 p0, p1;
            p0.x = epi<OP>(acc[mt][nt][0], b0v);
            p0.y = epi<OP>(acc[mt][nt][1], b1v);
            p1.x = epi<OP>(acc[mt][nt][2], b0v);
            p1.y = epi<OP>(acc[mt][nt][3], b1v);
            *(float2*)&C[r0 * ldc + c0]       = p0;
            *(float2*)&C[(r0 + 8) * ldc + c0] = p1;
        }
    }
}

// ---------------- fused flash attention ----------------
// Per block: one (b,h) batch, one 128-row q tile. Stream 16 kv tiles of 128.
// S = Q K^T * 0.125 + bias -> online softmax -> O += P V.  All mma tf32.
// 8 warps, each owns 16 q rows (full 128 kv cols of S, full 64 hd cols of O).
// smem: Ks[kv128][hd64] s68, Vs[kv128][hd64] s72, Ps[q128][kv128] s132, bias 256.
#define FA_KS_OFF 0
#define FA_VS_OFF (128*68)
#define FA_PS_OFF (FA_VS_OFF + 128*72)
#define FA_BI_OFF (FA_PS_OFF + 128*132)
#define FA_SMEM_BYTES ((FA_BI_OFF + 256) * 4)

extern __shared__ unsigned fa_sm[];

__global__ void __launch_bounds__(256)
flash_attn(const float* __restrict__ qkv, const float* __restrict__ bt,
           float* __restrict__ ctx)
{
    unsigned* Ks = fa_sm + FA_KS_OFF;
    unsigned* Vs = fa_sm + FA_VS_OFF;
    unsigned* Ps = fa_sm + FA_PS_OFF;
    float* bias_s = (float*)(fa_sm + FA_BI_OFF);

    const int z = blockIdx.y;
    const int b = z >> 4, h = z & 15;
    const int q0 = blockIdx.x * 128;
    const int t = threadIdx.x, lane = t & 31, wid = t >> 5;
    const int gid = lane >> 2, tig = lane & 3;
    const int wm = wid * 16;
    const int ld = 3 * D_;

    const float* Qg = qkv + (long)b * L_ * ld + (long)h * HD_;
    const float* Kg = Qg + D_;
    const float* Vg = Qg + 2 * D_;

    // Q fragments in registers (reused across all kv tiles)
    unsigned qf[8][4];
    {
        const float* r0p = Qg + (long)(q0 + wm + gid) * ld;
        const float* r1p = r0p + 8L * ld;
#pragma unroll
        for (int kk = 0; kk < 8; kk++) {
            qf[kk][0] = f2tf(r0p[kk * 8 + tig]);
            qf[kk][1] = f2tf(r1p[kk * 8 + tig]);
            qf[kk][2] = f2tf(r0p[kk * 8 + tig + 4]);
            qf[kk][3] = f2tf(r1p[kk * 8 + tig + 4]);
        }
    }

    float m0 = -1e30f, m1 = -1e30f, l0 = 0.f, l1 = 0.f;
    float o[8][4];
#pragma unroll
    for (int i = 0; i < 8; i++)
#pragma unroll
        for (int j = 0; j < 4; j++) o[i][j] = 0.f;

    // prefetch K tile 0 into regs
    float4 kv[8];
#pragma unroll
    for (int i = 0; i < 8; i++) {
        int idx = t + i * 256;
        kv[i] = *(const float4*)(Kg + (long)(idx >> 4) * ld + ((idx & 15) << 2));
    }

    for (int kt = 0; kt < 16; kt++) {
        __syncthreads();   // smem free of previous tile readers
        // K regs -> smem
#pragma unroll
        for (int i = 0; i < 8; i++) {
            int idx = t + i * 256;
            *(uint4*)&Ks[(idx >> 4) * 68 + ((idx & 15) << 2)] =
                make_uint4(f2tf(kv[i].x), f2tf(kv[i].y), f2tf(kv[i].z), f2tf(kv[i].w));
        }
        // bias slice for this tile: bias_s[j], j = ck - lr + 127
        if (t < 255) {
            int rel = kt * 128 - q0 + 384 + t;
            rel = min(max(rel, 0), 1022);
            bias_s[t] = bt[rel * 16 + h];
        }
        __syncthreads();

        // issue V loads (overlap with S compute)
        {
            const float* Vt = Vg + (long)kt * 128 * ld;
#pragma unroll
            for (int i = 0; i < 8; i++) {
                int idx = t + i * 256;
                kv[i] = *(const float4*)(Vt + (long)(idx >> 4) * ld + ((idx & 15) << 2));
            }
        }

        // S = Q @ K^T  (warp: rows wm..wm+15, cols 0..127)
        float s[16][4];
#pragma unroll
        for (int i = 0; i < 16; i++)
#pragma unroll
            for (int j = 0; j < 4; j++) s[i][j] = 0.f;
#pragma unroll
        for (int kk = 0; kk < 8; kk++) {
            const int k = kk * 8;
#pragma unroll
            for (int nt = 0; nt < 16; nt++) {
                unsigned bf[2];
                int cb = nt * 8 + gid;
                bf[0] = Ks[cb * 68 + k + tig];
                bf[1] = Ks[cb * 68 + k + tig + 4];
                mma_tf32(s[nt], qf[kk], bf);
            }
        }

        // scale + bias, row max
        float mx0 = -1e30f, mx1 = -1e30f;
        const int jb0 = 2 * tig - wm - gid + 127;   // + nt*8 for s0
#pragma unroll
        for (int nt = 0; nt < 16; nt++) {
            int j0 = jb0 + nt * 8;
            s[nt][0] = s[nt][0] * 0.125f + bias_s[j0];
            s[nt][1] = s[nt][1] * 0.125f + bias_s[j0 + 1];
            s[nt][2] = s[nt][2] * 0.125f + bias_s[j0 - 8];
            s[nt][3] = s[nt][3] * 0.125f + bias_s[j0 - 7];
            mx0 = fmaxf(mx0, fmaxf(s[nt][0], s[nt][1]));
            mx1 = fmaxf(mx1, fmaxf(s[nt][2], s[nt][3]));
        }
        mx0 = fmaxf(mx0, __shfl_xor_sync(0xffffffffu, mx0, 1));
        mx0 = fmaxf(mx0, __shfl_xor_sync(0xffffffffu, mx0, 2));
        mx1 = fmaxf(mx1, __shfl_xor_sync(0xffffffffu, mx1, 1));
        mx1 = fmaxf(mx1, __shfl_xor_sync(0xffffffffu, mx1, 2));

        float mn0 = fmaxf(m0, mx0), mn1 = fmaxf(m1, mx1);
        float a0 = __expf(m0 - mn0), a1 = __expf(m1 - mn1);
        m0 = mn0; m1 = mn1;

        float sum0 = 0.f, sum1 = 0.f;
#pragma unroll
        for (int nt = 0; nt < 16; nt++) {
            s[nt][0] = __expf(s[nt][0] - mn0);
            s[nt][1] = __expf(s[nt][1] - mn0);
            s[nt][2] = __expf(s[nt][2] - mn1);
            s[nt][3] = __expf(s[nt][3] - mn1);
            sum0 += s[nt][0] + s[nt][1];
            sum1 += s[nt][2] + s[nt][3];
        }
        sum0 += __shfl_xor_sync(0xffffffffu, sum0, 1);
        sum0 += __shfl_xor_sync(0xffffffffu, sum0, 2);
        sum1 += __shfl_xor_sync(0xffffffffu, sum1, 1);
        sum1 += __shfl_xor_sync(0xffffffffu, sum1, 2);
        l0 = l0 * a0 + sum0;
        l1 = l1 * a1 + sum1;
#pragma unroll
        for (int nt = 0; nt < 8; nt++) {
            o[nt][0] *= a0; o[nt][1] *= a0;
            o[nt][2] *= a1; o[nt][3] *= a1;
        }

        // P -> smem (A-operand layout), V regs -> smem
        {
            const int r0 = (wm + gid) * 132, r1 = (wm + gid + 8) * 132;
#pragma unroll
            for (int nt = 0; nt < 16; nt++) {
                int c = nt * 8 + 2 * tig;
                *(uint2*)&Ps[r0 + c] = make_uint2(f2tf(s[nt][0]), f2tf(s[nt][1]));
                *(uint2*)&Ps[r1 + c] = make_uint2(f2tf(s[nt][2]), f2tf(s[nt][3]));
            }
        }
#pragma unroll
        for (int i = 0; i < 8; i++) {
            int idx = t + i * 256;
            *(uint4*)&Vs[(idx >> 4) * 72 + ((idx & 15) << 2)] =
                make_uint4(f2tf(kv[i].x), f2tf(kv[i].y), f2tf(kv[i].z), f2tf(kv[i].w));
        }
        __syncthreads();

        // prefetch next K tile (overlap with PV compute)
        if (kt < 15) {
            const float* Kt = Kg + (long)(kt + 1) * 128 * ld;
#pragma unroll
            for (int i = 0; i < 8; i++) {
                int idx = t + i * 256;
                kv[i] = *(const float4*)(Kt + (long)(idx >> 4) * ld + ((idx & 15) << 2));
            }
        }

        // O += P @ V
#pragma unroll
        for (int kk = 0; kk < 16; kk++) {
            const int k = kk * 8;
            unsigned af[4];
            af[0] = Ps[(wm + gid) * 132 + k + tig];
            af[1] = Ps[(wm + gid + 8) * 132 + k + tig];
            af[2] = Ps[(wm + gid) * 132 + k + tig + 4];
            af[3] = Ps[(wm + gid + 8) * 132 + k + tig + 4];
#pragma unroll
            for (int nt = 0; nt < 8; nt++) {
                unsigned bf[2];
                int cb = nt * 8 + gid;
                bf[0] = Vs[(k + tig) * 72 + cb];
                bf[1] = Vs[(k + tig + 4) * 72 + cb];
                mma_tf32(o[nt], af, bf);
            }
        }
    }

    // normalize and write ctx[b, q0+row, h*64 + col]
    const float inv0 = 1.0f / l0, inv1 = 1.0f / l1;
    float* C0 = ctx + ((long)b * L_ + q0 + wm + gid) * D_ + h * HD_;
    float* C1 = C0 + 8L * D_;
#pragma unroll
    for (int nt = 0; nt < 8; nt++) {
        int c = nt * 8 + 2 * tig;
        *(float2*)&C0[c] = make_float2(o[nt][0] * inv0, o[nt][1] * inv0);
        *(float2*)&C1[c] = make_float2(o[nt][2] * inv1, o[nt][3] * inv1);
    }
}

// ---------------- residual add + LayerNorm ----------------
__global__ void __launch_bounds__(256)
add_ln(const float* __restrict__ X, const float* __restrict__ Y,
       const float* __restrict__ gamma, const float* __restrict__ beta,
       float* __restrict__ O)
{
    const long r = blockIdx.x;
    const int t = threadIdx.x;
    __shared__ float red[16];

    float4 a = *(const float4*)(X + r * D_ + t * 4);
    float4 b = *(const float4*)(Y + r * D_ + t * 4);
    float v[4] = {a.x + b.x, a.y + b.y, a.z + b.z, a.w + b.w};

    float s = v[0] + v[1] + v[2] + v[3];
    float s2 = v[0]*v[0] + v[1]*v[1] + v[2]*v[2] + v[3]*v[3];
#pragma unroll
    for (int off = 16; off > 0; off >>= 1) {
        s  += __shfl_xor_sync(0xffffffffu, s, off);
        s2 += __shfl_xor_sync(0xffffffffu, s2, off);
    }
    if ((t & 31) == 0) { red[t >> 5] = s; red[8 + (t >> 5)] = s2; }
    __syncthreads();
    float S = 0.f, S2 = 0.f;
#pragma unroll
    for (int i = 0; i < 8; i++) { S += red[i]; S2 += red[8 + i]; }
    const float mean = S * (1.0f / D_);
    const float var  = S2 * (1.0f / D_) - mean * mean;
    const float rinv = rsqrtf(var + 1e-5f);

    float4 g  = *(const float4*)(gamma + t * 4);
    float4 be = *(const float4*)(beta + t * 4);
    float4 o;
    o.x = (v[0] - mean) * rinv * g.x + be.x;
    o.y = (v[1] - mean) * rinv * g.y + be.y;
    o.z = (v[2] - mean) * rinv * g.z + be.z;
    o.w = (v[3] - mean) * rinv * g.w + be.w;
    *(float4*)(O + r * D_ + t * 4) = o;
}

// ---------------- launcher ----------------
extern "C" void kernel_launch(void* const* d_in, const int* in_sizes, int n_in,
                              void* d_out, int out_size)
{
    const float* x     = (const float*)d_in[0];
    const float* w_qkv = (const float*)d_in[1];
    const float* w_out = (const float*)d_in[2];
    const float* b_out = (const float*)d_in[3];
    const float* bt    = (const float*)d_in[4];
    const float* g1    = (const float*)d_in[5];
    const float* be1   = (const float*)d_in[6];
    const float* w1    = (const float*)d_in[7];
    const float* bf1   = (const float*)d_in[8];
    const float* w2    = (const float*)d_in[9];
    const float* bf2   = (const float*)d_in[10];
    const float* g2    = (const float*)d_in[11];
    const float* be2   = (const float*)d_in[12];
    float* out = (float*)d_out;

    float *qkv, *ctx, *x1, *hh, *tt;
    cudaGetSymbolAddress((void**)&qkv, g_qkv);
    cudaGetSymbolAddress((void**)&ctx, g_ctx);
    cudaGetSymbolAddress((void**)&x1,  g_x1);
    cudaGetSymbolAddress((void**)&hh,  g_h);
    cudaGetSymbolAddress((void**)&tt,  g_t);

    static int fa_attr_set = 0;
    if (!fa_attr_set) {
        cudaFuncSetAttribute(flash_attn, cudaFuncAttributeMaxDynamicSharedMemorySize,
                             FA_SMEM_BYTES);
        fa_attr_set = 1;
    }

    // 1) qkv = x @ w_qkv
    gemm_tf32<0><<<dim3(3 * D_ / 128, M_ / 128), 256>>>(
        x, w_qkv, nullptr, qkv, D_, D_, 3 * D_, 3 * D_);

    // 2) fused attention -> ctx
    flash_attn<<<dim3(L_ / 128, B_ * H_), 256, FA_SMEM_BYTES>>>(qkv, bt, ctx);

    // 3) attn_out = ctx @ w_out + b_out
    gemm_tf32<1><<<dim3(D_ / 128, M_ / 128), 256>>>(
        ctx, w_out, b_out, tt, D_, D_, D_, D_);

    // 4) x1 = LN(x + attn_out)
    add_ln<<<M_, 256>>>(x, tt, g1, be1, x1);

    // 5) h = gelu(x1 @ w_ff1 + b_ff1)
    gemm_tf32<2><<<dim3(DFF_ / 128, M_ / 128), 256>>>(
        x1, w1, bf1, hh, D_, D_, DFF_, DFF_);

    // 6) ffn_out = h @ w_ff2 + b_ff2
    gemm_tf32<1><<<dim3(D_ / 128, M_ / 128), 256>>>(
        hh, w2, bf2, tt, DFF_, DFF_, D_, D_);

    // 7) out = LN(x1 + ffn_out)
    add_ln<<<M_, 256>>>(x1, tt, g2, be2, out);
}